// round 3
// baseline (speedup 1.0000x reference)
#include <cuda_runtime.h>

// Problem dims (fixed by the reference setup_inputs)
#define TB 4      // batch
#define TT 512    // tokens
#define TD 1024   // d_model
#define TNC 16    // n_concepts
#define TH 256    // init_size
#define NBATCH (TB * TNC)   // 64 independent (b,n) GEMM batches

// Scratch (allocation-free rule: __device__ globals)
__device__ float g_wq[(size_t)NBATCH * TT * TH];        // 33.5 MB: wq[b,n,t,h]
__device__ float g_attn_fb[(size_t)NBATCH * TT * TT];   // 67 MB fallback if d_out has no attn slot

// -------- register-tiled fp32 GEMM: C[M,N] = A[M,K] * B, 128x128x8 tile, TM=TN=8 --------
constexpr int BM = 128, BNT = 128, BK = 8, TM = 8, TN = 8;
constexpr int NTHREADS = (BM / TM) * (BNT / TN);  // 256

// TRANSB=false: B is [K, Ncols] row-major (ldb = row stride)
// TRANSB=true : B is [Ncols, K] row-major (C = A * B^T), used for wq @ wq^T
template <bool TRANSB>
__device__ __forceinline__ void gemm_tile(const float* __restrict__ A,
                                          const float* __restrict__ Bm,
                                          float* __restrict__ C,
                                          int K, int lda, int ldb, int ldc) {
    __shared__ float As[BK * BM];   // transposed: As[k][m]
    __shared__ float Bs[BK * BNT];  // Bs[k][n]

    const int tid  = threadIdx.x;
    const int tCol = tid & 15;   // 16 thread-cols
    const int tRow = tid >> 4;   // 16 thread-rows
    const int m0 = blockIdx.y * BM;
    const int n0 = blockIdx.x * BNT;

    // A tile load map: 128 rows x 8 cols as float4 (2 threads per row)
    const int aRow = tid >> 1;
    const int aCol = (tid & 1) * 4;
    // B tile load maps
    const int bRowT = tid >> 1;         // TRANSB: output-col index
    const int bColT = (tid & 1) * 4;    // TRANSB: k offset
    const int bRowN = tid >> 5;         // !TRANSB: k index
    const int bColN = (tid & 31) * 4;   // !TRANSB: n offset

    float acc[TM][TN];
#pragma unroll
    for (int i = 0; i < TM; i++)
#pragma unroll
        for (int j = 0; j < TN; j++) acc[i][j] = 0.0f;

    for (int k0 = 0; k0 < K; k0 += BK) {
        // --- stage A (transpose into SMEM) ---
        float4 a = *reinterpret_cast<const float4*>(
            &A[(size_t)(m0 + aRow) * lda + k0 + aCol]);
        As[(aCol + 0) * BM + aRow] = a.x;
        As[(aCol + 1) * BM + aRow] = a.y;
        As[(aCol + 2) * BM + aRow] = a.z;
        As[(aCol + 3) * BM + aRow] = a.w;
        // --- stage B ---
        if (TRANSB) {
            float4 b = *reinterpret_cast<const float4*>(
                &Bm[(size_t)(n0 + bRowT) * ldb + k0 + bColT]);
            Bs[(bColT + 0) * BNT + bRowT] = b.x;
            Bs[(bColT + 1) * BNT + bRowT] = b.y;
            Bs[(bColT + 2) * BNT + bRowT] = b.z;
            Bs[(bColT + 3) * BNT + bRowT] = b.w;
        } else {
            float4 b = *reinterpret_cast<const float4*>(
                &Bm[(size_t)(k0 + bRowN) * ldb + n0 + bColN]);
            *reinterpret_cast<float4*>(&Bs[bRowN * BNT + bColN]) = b;
        }
        __syncthreads();

#pragma unroll
        for (int k = 0; k < BK; k++) {
            float regM[TM], regN[TN];
            *reinterpret_cast<float4*>(&regM[0]) =
                *reinterpret_cast<const float4*>(&As[k * BM + tRow * TM]);
            *reinterpret_cast<float4*>(&regM[4]) =
                *reinterpret_cast<const float4*>(&As[k * BM + tRow * TM + 4]);
            *reinterpret_cast<float4*>(&regN[0]) =
                *reinterpret_cast<const float4*>(&Bs[k * BNT + tCol * TN]);
            *reinterpret_cast<float4*>(&regN[4]) =
                *reinterpret_cast<const float4*>(&Bs[k * BNT + tCol * TN + 4]);
#pragma unroll
            for (int i = 0; i < TM; i++)
#pragma unroll
                for (int j = 0; j < TN; j++)
                    acc[i][j] = fmaf(regM[i], regN[j], acc[i][j]);
        }
        __syncthreads();
    }

#pragma unroll
    for (int i = 0; i < TM; i++) {
#pragma unroll
        for (int j = 0; j < TN; j += 4) {
            float4 v = make_float4(acc[i][j], acc[i][j + 1], acc[i][j + 2], acc[i][j + 3]);
            *reinterpret_cast<float4*>(
                &C[(size_t)(m0 + tRow * TM + i) * ldc + n0 + tCol * TN + j]) = v;
        }
    }
}

// -------- kernel 1: wq[z] = x[b] @ w_qs[n]   (M=512, N=256, K=1024) --------
__global__ __launch_bounds__(NTHREADS) void k_wq(const float* __restrict__ x,
                                                 const float* __restrict__ wqs) {
    const int z = blockIdx.z;
    const int b = z >> 4;
    const int n = z & 15;
    gemm_tile<false>(x + (size_t)b * TT * TD,
                     wqs + (size_t)n * TD * TH,
                     g_wq + (size_t)z * TT * TH,
                     TD, TD, TH, TH);
}

// -------- kernel 2: logits[z] = wq[z] @ wq[z]^T  (M=N=512, K=256) --------
__global__ __launch_bounds__(NTHREADS) void k_logits(float* __restrict__ attn) {
    const int z = blockIdx.z;
    const float* wq = g_wq + (size_t)z * TT * TH;
    gemm_tile<true>(wq, wq, attn + (size_t)z * TT * TT, TH, TH, TH, TT);
}

// -------- kernel 3: row softmax over last axis (rows of length 512) --------
__global__ __launch_bounds__(256) void k_softmax(float* __restrict__ attn) {
    __shared__ float redm[8];
    __shared__ float reds[8];
    float* p = attn + (size_t)blockIdx.x * TT;
    const int tid = threadIdx.x;

    float v0 = p[tid];
    float v1 = p[tid + 256];
    float m = fmaxf(v0, v1);
#pragma unroll
    for (int o = 16; o; o >>= 1) m = fmaxf(m, __shfl_xor_sync(0xffffffffu, m, o));
    if ((tid & 31) == 0) redm[tid >> 5] = m;
    __syncthreads();
    float mAll = redm[0];
#pragma unroll
    for (int w = 1; w < 8; w++) mAll = fmaxf(mAll, redm[w]);

    float e0 = expf(v0 - mAll);
    float e1 = expf(v1 - mAll);
    float s = e0 + e1;
#pragma unroll
    for (int o = 16; o; o >>= 1) s += __shfl_xor_sync(0xffffffffu, s, o);
    if ((tid & 31) == 0) reds[tid >> 5] = s;
    __syncthreads();
    float sAll = 0.0f;
#pragma unroll
    for (int w = 0; w < 8; w++) sAll += reds[w];
    const float inv = 1.0f / sAll;
    p[tid] = e0 * inv;
    p[tid + 256] = e1 * inv;
}

// -------- kernel 4: e[z] = attn[z] @ x[b]   (M=512, N=1024, K=512) --------
__global__ __launch_bounds__(NTHREADS) void k_eagg(const float* __restrict__ attn,
                                                   const float* __restrict__ x,
                                                   float* __restrict__ out) {
    const int z = blockIdx.z;
    const int b = z >> 4;
    gemm_tile<false>(attn + (size_t)z * TT * TT,
                     x + (size_t)b * TT * TD,
                     out + (size_t)z * TT * TD,
                     TT, TT, TD, TD);
}

extern "C" void kernel_launch(void* const* d_in, const int* in_sizes, int n_in,
                              void* d_out, int out_size) {
    (void)in_sizes; (void)n_in;
    const float* x   = (const float*)d_in[0];
    const float* wqs = (const float*)d_in[1];
    // d_in[2] = w_ks: unused in the reference math (source bug kept faithfully)
    float* out = (float*)d_out;

    const long long EAGG = (long long)NBATCH * TT * TD;  // 33,554,432
    const long long ATTN = (long long)NBATCH * TT * TT;  // 16,777,216

    // attn destination: second output slot of d_out if present, else scratch
    float* attn;
    if ((long long)out_size >= EAGG + ATTN) {
        attn = out + EAGG;
    } else {
        void* p = nullptr;
        cudaGetSymbolAddress(&p, g_attn_fb);
        attn = (float*)p;
    }

    dim3 thr(NTHREADS);
    dim3 g1(TH / BNT, TT / BM, NBATCH);   // (2, 4, 64)
    dim3 g2(TT / BNT, TT / BM, NBATCH);   // (4, 4, 64)
    dim3 g3(TD / BNT, TT / BM, NBATCH);   // (8, 4, 64)

    k_wq<<<g1, thr>>>(x, wqs);
    k_logits<<<g2, thr>>>(attn);
    k_softmax<<<NBATCH * TT, 256>>>(attn);
    k_eagg<<<g3, thr>>>(attn, x, out);
}

// round 7
// speedup vs baseline: 1.0452x; 1.0452x over previous
#include <cuda_runtime.h>
#include <cstdint>

// Problem dims (fixed by reference setup_inputs)
#define TB 4      // batch
#define TT 512    // tokens
#define TD 1024   // d_model
#define TNC 16    // n_concepts
#define TH 256    // init_size
#define NBATCH (TB * TNC)   // 64 batched GEMMs

// ---------------- scratch (__device__ globals; allocation-free rule) ----------------
__device__ float g_wq[(size_t)NBATCH * TT * TH];      // fp32 wq[z][t][h]
__device__ float g_attn_fb[(size_t)NBATCH * TT * TT]; // fp32 attn if d_out has no slot

// ---------------- tf32 helpers ----------------
__device__ __forceinline__ uint32_t tf32_of(float v) {
    uint32_t r;
    asm("cvt.rna.tf32.f32 %0, %1;" : "=r"(r) : "f"(v));
    return r;
}
__device__ __forceinline__ void tf32_split(float v, uint32_t& hi, uint32_t& lo) {
    hi = tf32_of(v);
    lo = tf32_of(v - __uint_as_float(hi));
}
__device__ __forceinline__ void mma_tf32(float* d, const uint32_t* a, const uint32_t* b) {
    asm volatile(
        "mma.sync.aligned.m16n8k8.row.col.f32.tf32.tf32.f32 "
        "{%0,%1,%2,%3}, {%4,%5,%6,%7}, {%8,%9}, {%0,%1,%2,%3};"
        : "+f"(d[0]), "+f"(d[1]), "+f"(d[2]), "+f"(d[3])
        : "r"(a[0]), "r"(a[1]), "r"(a[2]), "r"(a[3]), "r"(b[0]), "r"(b[1]));
}

// ---------------- tf32x3 batched GEMM: C tile 128x128 = A[M,K] * B(k,n) ----------------
// A source is ALWAYS row-major [m][k]. B source:
//   MODE 1: w_qs[n_c][d][h] -> (k=d, n=h): [k][n] row-major, DIRECT copy to Bs
//   MODE 2: wq[t][h]        -> (n=t, k=h): [n][k] row-major, SCATTER (transpose) to Bs
//   MODE 3: x[t][d]         -> (k=t, n=d): [k][n] row-major, DIRECT
// SMEM: As[128][20] (pad 20 -> conflict-free A frag loads), Bs[16][132].
constexpr int APAD = 20, BPAD = 132;

template <int MODE>
__global__ __launch_bounds__(256) void k_gemm_tf32(const float* __restrict__ Ain,
                                                   const float* __restrict__ Bin,
                                                   float* __restrict__ Cout) {
    constexpr int K   = (MODE == 1) ? TD : (MODE == 2) ? TH : TT;
    constexpr int NKB = K / 16;
    constexpr int LDA = K;
    constexpr int LDB = (MODE == 1) ? TH : (MODE == 2) ? TH : TD;
    constexpr int LDC = (MODE == 1) ? TH : (MODE == 2) ? TT : TD;

    __shared__ uint32_t sAh[128][APAD], sAl[128][APAD];
    __shared__ uint32_t sBh[16][BPAD],  sBl[16][BPAD];

    const int tid = threadIdx.x, wid = tid >> 5, lane = tid & 31;
    const int wm = wid & 1, wn = wid >> 1;   // 2x4 warp grid, warp tile 64x32
    const int lr = lane >> 2, lq = lane & 3;
    const int z = blockIdx.z;
    const int m0 = blockIdx.y * 128;
    const int n0 = blockIdx.x * 128;

    // batch bases
    size_t aoff, boff;
    if constexpr (MODE == 1) {        // A = x[b], B = w_qs[n_c]
        aoff = (size_t)(z >> 4) * TT * TD;
        boff = (size_t)(z & 15) * TD * TH;
    } else if constexpr (MODE == 2) { // A = B = wq[z]
        aoff = (size_t)z * TT * TH;
        boff = aoff;
    } else {                          // A = attn[z], B = x[b]
        aoff = (size_t)z * TT * TT;
        boff = (size_t)(z >> 4) * TT * TD;
    }
    const float* pA = Ain + aoff + (size_t)m0 * LDA;
    const float* pB = (MODE == 2) ? (Bin + boff + (size_t)n0 * LDB)  // [n][k]: row offset
                                  : (Bin + boff + n0);               // [k][n]: col offset

    float acc[4][4][4];
#pragma unroll
    for (int mi = 0; mi < 4; mi++)
#pragma unroll
        for (int ni = 0; ni < 4; ni++)
#pragma unroll
            for (int e = 0; e < 4; e++) acc[mi][ni][e] = 0.0f;

    // ---- staging: register prefetch of one 16-wide K block (A: 128x16, B: 16x128) ----
    float4 pfA[2], pfB[2];
    auto prefetch = [&](int kb) {
#pragma unroll
        for (int i = 0; i < 2; i++) {
            const int cid = tid + i * 256;          // 512 float4 chunks each
            const int ar = cid >> 2, ac4 = cid & 3; // A: row, k-chunk
            pfA[i] = *reinterpret_cast<const float4*>(pA + (size_t)ar * LDA + kb * 16 + ac4 * 4);
            if constexpr (MODE == 2) {
                const int nr = cid >> 2, kc4 = cid & 3;  // B[n][k]
                pfB[i] = *reinterpret_cast<const float4*>(pB + (size_t)nr * LDB + kb * 16 + kc4 * 4);
            } else {
                const int kr = cid >> 5, nc4 = cid & 31; // B[k][n]
                pfB[i] = *reinterpret_cast<const float4*>(pB + (size_t)(kb * 16 + kr) * LDB + nc4 * 4);
            }
        }
    };
    auto store_stage = [&]() {
#pragma unroll
        for (int i = 0; i < 2; i++) {
            const int cid = tid + i * 256;
            const int ar = cid >> 2, ac4 = cid & 3;
            const float av[4] = {pfA[i].x, pfA[i].y, pfA[i].z, pfA[i].w};
#pragma unroll
            for (int e = 0; e < 4; e++)
                tf32_split(av[e], sAh[ar][ac4 * 4 + e], sAl[ar][ac4 * 4 + e]);
            const float bv[4] = {pfB[i].x, pfB[i].y, pfB[i].z, pfB[i].w};
            if constexpr (MODE == 2) {
                const int nr = cid >> 2, kc4 = cid & 3;
#pragma unroll
                for (int e = 0; e < 4; e++)
                    tf32_split(bv[e], sBh[kc4 * 4 + e][nr], sBl[kc4 * 4 + e][nr]);
            } else {
                const int kr = cid >> 5, nc4 = cid & 31;
#pragma unroll
                for (int e = 0; e < 4; e++)
                    tf32_split(bv[e], sBh[kr][nc4 * 4 + e], sBl[kr][nc4 * 4 + e]);
            }
        }
    };

    prefetch(0);

#pragma unroll 1
    for (int kb = 0; kb < NKB; kb++) {
        store_stage();
        __syncthreads();
        if (kb + 1 < NKB) prefetch(kb + 1);   // LDG latency hides under MMAs

#pragma unroll
        for (int k8 = 0; k8 < 2; k8++) {
            const int ko = k8 * 8;
            uint32_t ah[4][4], al[4][4], bh[4][2], bl[4][2];
#pragma unroll
            for (int mi = 0; mi < 4; mi++) {
                const int row = wm * 64 + mi * 16 + lr;
                ah[mi][0] = sAh[row][ko + lq];      al[mi][0] = sAl[row][ko + lq];
                ah[mi][1] = sAh[row + 8][ko + lq];  al[mi][1] = sAl[row + 8][ko + lq];
                ah[mi][2] = sAh[row][ko + lq + 4];  al[mi][2] = sAl[row][ko + lq + 4];
                ah[mi][3] = sAh[row + 8][ko + lq + 4]; al[mi][3] = sAl[row + 8][ko + lq + 4];
            }
#pragma unroll
            for (int ni = 0; ni < 4; ni++) {
                const int n = wn * 32 + ni * 8 + lr;
                bh[ni][0] = sBh[ko + lq][n];     bl[ni][0] = sBl[ko + lq][n];
                bh[ni][1] = sBh[ko + lq + 4][n]; bl[ni][1] = sBl[ko + lq + 4][n];
            }
#pragma unroll
            for (int mi = 0; mi < 4; mi++)
#pragma unroll
                for (int ni = 0; ni < 4; ni++) {
                    mma_tf32(acc[mi][ni], ah[mi], bh[ni]);  // hi*hi
                    mma_tf32(acc[mi][ni], ah[mi], bl[ni]);  // hi*lo
                    mma_tf32(acc[mi][ni], al[mi], bh[ni]);  // lo*hi
                }
        }
        __syncthreads();
    }

    // ---- epilogue: fp32 float2 stores ----
    const int rbase = m0 + wm * 64 + lr;
    const int cbase = n0 + wn * 32 + lq * 2;
#pragma unroll
    for (int mi = 0; mi < 4; mi++)
#pragma unroll
        for (int ni = 0; ni < 4; ni++)
#pragma unroll
            for (int h = 0; h < 2; h++) {
                const int row = rbase + mi * 16 + h * 8;
                const int col = cbase + ni * 8;
                float* dst = Cout + (size_t)z * TT * LDC + (size_t)row * LDC + col;
                *reinterpret_cast<float2*>(dst) =
                    make_float2(acc[mi][ni][2 * h], acc[mi][ni][2 * h + 1]);
            }
}

// ---------------- softmax over rows of 512 (identical to the round-3 PASSING kernel) ----------------
__global__ __launch_bounds__(256) void k_softmax(float* __restrict__ attn) {
    __shared__ float redm[8];
    __shared__ float reds[8];
    float* p = attn + (size_t)blockIdx.x * TT;
    const int tid = threadIdx.x;

    float v0 = p[tid];
    float v1 = p[tid + 256];
    float m = fmaxf(v0, v1);
#pragma unroll
    for (int o = 16; o; o >>= 1) m = fmaxf(m, __shfl_xor_sync(0xffffffffu, m, o));
    if ((tid & 31) == 0) redm[tid >> 5] = m;
    __syncthreads();
    float mAll = redm[0];
#pragma unroll
    for (int w = 1; w < 8; w++) mAll = fmaxf(mAll, redm[w]);

    float e0 = expf(v0 - mAll);
    float e1 = expf(v1 - mAll);
    float s = e0 + e1;
#pragma unroll
    for (int o = 16; o; o >>= 1) s += __shfl_xor_sync(0xffffffffu, s, o);
    if ((tid & 31) == 0) reds[tid >> 5] = s;
    __syncthreads();
    float sAll = 0.0f;
#pragma unroll
    for (int w = 0; w < 8; w++) sAll += reds[w];
    const float inv = 1.0f / sAll;
    p[tid] = e0 * inv;
    p[tid + 256] = e1 * inv;
}

// ---------------- launcher (identical structure to the round-3 PASSING launcher) ----------------
extern "C" void kernel_launch(void* const* d_in, const int* in_sizes, int n_in,
                              void* d_out, int out_size) {
    (void)in_sizes; (void)n_in;
    const float* x   = (const float*)d_in[0];
    const float* wqs = (const float*)d_in[1];
    // d_in[2] = w_ks: unused in reference math (faithful to source bug)
    float* out = (float*)d_out;

    const long long EAGG = (long long)NBATCH * TT * TD;  // 33,554,432
    const long long ATTN = (long long)NBATCH * TT * TT;  // 16,777,216

    float* attn;
    if ((long long)out_size >= EAGG + ATTN) {
        attn = out + EAGG;
    } else {
        void* p = nullptr;
        cudaGetSymbolAddress(&p, g_attn_fb);
        attn = (float*)p;
    }
    void* wqp = nullptr;
    cudaGetSymbolAddress(&wqp, g_wq);
    float* wq = (float*)wqp;

    // GEMM1: wq = x @ w_qs          (A=x[b] row-major [t][d], B=w_qs[n] [d][h] direct)
    k_gemm_tf32<1><<<dim3(TH / 128, TT / 128, NBATCH), 256>>>(x, wqs, wq);
    // GEMM2: logits = wq @ wq^T     (A=wq [t][h], B=wq [t][h] scatter-transposed)
    k_gemm_tf32<2><<<dim3(TT / 128, TT / 128, NBATCH), 256>>>(wq, wq, attn);
    // softmax in place
    k_softmax<<<NBATCH * TT, 256>>>(attn);
    // GEMM3: e = attn @ x           (A=attn [s][t], B=x[b] [t][d] direct)
    k_gemm_tf32<3><<<dim3(TD / 128, TT / 128, NBATCH), 256>>>(attn, x, out);
}

// round 8
// speedup vs baseline: 1.3990x; 1.3384x over previous
#include <cuda_runtime.h>
#include <cstdint>

// Problem dims (fixed by reference setup_inputs)
#define TB 4      // batch
#define TT 512    // tokens
#define TD 1024   // d_model
#define TNC 16    // n_concepts
#define TH 256    // init_size
#define NBATCH (TB * TNC)   // 64 batched GEMMs

// ---------------- scratch (__device__ globals; allocation-free rule) ----------------
__device__ float g_wq[(size_t)NBATCH * TT * TH];      // fp32 wq[z][t][h]
__device__ float g_attn_fb[(size_t)NBATCH * TT * TT]; // fp32 attn if d_out has no slot

// ---------------- helpers ----------------
__device__ __forceinline__ uint32_t smem_u32(const void* p) {
    uint32_t a;
    asm("{ .reg .u64 t; cvta.to.shared.u64 t, %1; cvt.u32.u64 %0, t; }" : "=r"(a) : "l"(p));
    return a;
}
__device__ __forceinline__ void cp16(uint32_t dst, const void* src) {
    asm volatile("cp.async.cg.shared.global [%0], [%1], 16;" :: "r"(dst), "l"(src) : "memory");
}
__device__ __forceinline__ void cp_commit() { asm volatile("cp.async.commit_group;" ::: "memory"); }
__device__ __forceinline__ void cp_wait0()  { asm volatile("cp.async.wait_group 0;" ::: "memory"); }

__device__ __forceinline__ uint32_t tf32_of(float v) {
    uint32_t r;
    asm("cvt.rna.tf32.f32 %0, %1;" : "=r"(r) : "f"(v));
    return r;
}
__device__ __forceinline__ void tf32_split(float v, uint32_t& hi, uint32_t& lo) {
    hi = tf32_of(v);
    lo = tf32_of(v - __uint_as_float(hi));
}
__device__ __forceinline__ void mma_tf32(float* d, const uint32_t* a, const uint32_t* b) {
    asm volatile(
        "mma.sync.aligned.m16n8k8.row.col.f32.tf32.tf32.f32 "
        "{%0,%1,%2,%3}, {%4,%5,%6,%7}, {%8,%9}, {%0,%1,%2,%3};"
        : "+f"(d[0]), "+f"(d[1]), "+f"(d[2]), "+f"(d[3])
        : "r"(a[0]), "r"(a[1]), "r"(a[2]), "r"(a[3]), "r"(b[0]), "r"(b[1]));
}

// ---------------- tf32x3 batched GEMM: C tile 128x128 = A[M,K] * B(k,n) ----------------
// A always row-major [m][k], staged as sA[128][20] fp32 (pad 20 -> conflict-free).
// B: MODE 1: w_qs [d][h] = [k][n] direct, staged [16][136]
//    MODE 2: wq   [t][h] = [n][k],        staged [128][20] (A-style)
//    MODE 3: x    [t][d] = [k][n] direct, staged [16][136]
// tf32 hi/lo split happens in REGISTERS at fragment-load time (SMEM holds raw fp32).
// 2-stage cp.async double buffer, one __syncthreads per K-block.
template <int MODE>
__global__ __launch_bounds__(256) void k_gemm_tf32(const float* __restrict__ Ain,
                                                   const float* __restrict__ Bin,
                                                   float* __restrict__ Cout) {
    constexpr int K   = (MODE == 1) ? TD : (MODE == 2) ? TH : TT;
    constexpr int NKB = K / 16;
    constexpr int LDA = K;
    constexpr int LDB = (MODE == 1) ? TH : (MODE == 2) ? TH : TD;
    constexpr int LDC = (MODE == 1) ? TH : (MODE == 2) ? TT : TD;
    constexpr bool BTR = (MODE == 2);          // B stored [n][k]
    constexpr int BR = BTR ? 128 : 16;
    constexpr int BC = BTR ? 20  : 136;

    __shared__ float sA[2][128][20];
    __shared__ float sB[2][BR][BC];

    const int tid = threadIdx.x, wid = tid >> 5, lane = tid & 31;
    const int wm = wid & 1, wn = wid >> 1;     // 2x4 warp grid, warp tile 64x32
    const int lr = lane >> 2, lq = lane & 3;
    const int z = blockIdx.z;
    const int m0 = blockIdx.y * 128;
    const int n0 = blockIdx.x * 128;

    size_t aoff, boff;
    if constexpr (MODE == 1) {
        aoff = (size_t)(z >> 4) * TT * TD;
        boff = (size_t)(z & 15) * TD * TH;
    } else if constexpr (MODE == 2) {
        aoff = (size_t)z * TT * TH;
        boff = aoff;
    } else {
        aoff = (size_t)z * TT * TT;
        boff = (size_t)(z >> 4) * TT * TD;
    }
    const float* pA = Ain + aoff + (size_t)m0 * LDA;
    const float* pB = BTR ? (Bin + boff + (size_t)n0 * LDB)   // [n][k] row offset
                          : (Bin + boff + n0);                // [k][n] col offset

    float acc[4][4][4];
#pragma unroll
    for (int mi = 0; mi < 4; mi++)
#pragma unroll
        for (int ni = 0; ni < 4; ni++)
#pragma unroll
            for (int e = 0; e < 4; e++) acc[mi][ni][e] = 0.0f;

    // per-thread: 2 x 16B chunks for A, 2 for B (512 chunks each side)
    auto issue_stage = [&](int kb, int s) {
#pragma unroll
        for (int i = 0; i < 2; i++) {
            const int cid = tid + i * 256;
            const int ar = cid >> 2, ac4 = cid & 3;
            cp16(smem_u32(&sA[s][ar][ac4 * 4]),
                 pA + (size_t)ar * LDA + kb * 16 + ac4 * 4);
            if constexpr (BTR) {
                const int nr = cid >> 2, kc4 = cid & 3;
                cp16(smem_u32(&sB[s][nr][kc4 * 4]),
                     pB + (size_t)nr * LDB + kb * 16 + kc4 * 4);
            } else {
                const int kr = cid >> 5, nc4 = cid & 31;
                cp16(smem_u32(&sB[s][kr][nc4 * 4]),
                     pB + (size_t)(kb * 16 + kr) * LDB + nc4 * 4);
            }
        }
        cp_commit();
    };

    issue_stage(0, 0);

#pragma unroll 1
    for (int kb = 0; kb < NKB; kb++) {
        const int s = kb & 1;
        cp_wait0();              // stage s data landed (only outstanding group)
        __syncthreads();         // visible to all; also: all warps done reading stage s^1
        if (kb + 1 < NKB) issue_stage(kb + 1, s ^ 1);

#pragma unroll
        for (int k8 = 0; k8 < 2; k8++) {
            const int ko = k8 * 8;
            uint32_t ah[4][4], al[4][4], bh[4][2], bl[4][2];
#pragma unroll
            for (int mi = 0; mi < 4; mi++) {
                const int row = wm * 64 + mi * 16 + lr;
                tf32_split(sA[s][row][ko + lq],         ah[mi][0], al[mi][0]);
                tf32_split(sA[s][row + 8][ko + lq],     ah[mi][1], al[mi][1]);
                tf32_split(sA[s][row][ko + lq + 4],     ah[mi][2], al[mi][2]);
                tf32_split(sA[s][row + 8][ko + lq + 4], ah[mi][3], al[mi][3]);
            }
#pragma unroll
            for (int ni = 0; ni < 4; ni++) {
                const int n = wn * 32 + ni * 8 + lr;
                float b0, b1;
                if constexpr (BTR) { b0 = sB[s][n][ko + lq]; b1 = sB[s][n][ko + lq + 4]; }
                else               { b0 = sB[s][ko + lq][n]; b1 = sB[s][ko + lq + 4][n]; }
                tf32_split(b0, bh[ni][0], bl[ni][0]);
                tf32_split(b1, bh[ni][1], bl[ni][1]);
            }
            // pass-major: dependent acc updates are 16 MMAs apart
#pragma unroll
            for (int mi = 0; mi < 4; mi++)
#pragma unroll
                for (int ni = 0; ni < 4; ni++)
                    mma_tf32(acc[mi][ni], ah[mi], bh[ni]);   // hi*hi
#pragma unroll
            for (int mi = 0; mi < 4; mi++)
#pragma unroll
                for (int ni = 0; ni < 4; ni++)
                    mma_tf32(acc[mi][ni], ah[mi], bl[ni]);   // hi*lo
#pragma unroll
            for (int mi = 0; mi < 4; mi++)
#pragma unroll
                for (int ni = 0; ni < 4; ni++)
                    mma_tf32(acc[mi][ni], al[mi], bh[ni]);   // lo*hi
        }
    }

    // ---- epilogue: fp32 float2 stores (identical to passing R7) ----
    const int rbase = m0 + wm * 64 + lr;
    const int cbase = n0 + wn * 32 + lq * 2;
#pragma unroll
    for (int mi = 0; mi < 4; mi++)
#pragma unroll
        for (int ni = 0; ni < 4; ni++)
#pragma unroll
            for (int h = 0; h < 2; h++) {
                const int row = rbase + mi * 16 + h * 8;
                const int col = cbase + ni * 8;
                float* dst = Cout + (size_t)z * TT * LDC + (size_t)row * LDC + col;
                *reinterpret_cast<float2*>(dst) =
                    make_float2(acc[mi][ni][2 * h], acc[mi][ni][2 * h + 1]);
            }
}

// ---------------- softmax over rows of 512 (unchanged, passing) ----------------
__global__ __launch_bounds__(256) void k_softmax(float* __restrict__ attn) {
    __shared__ float redm[8];
    __shared__ float reds[8];
    float* p = attn + (size_t)blockIdx.x * TT;
    const int tid = threadIdx.x;

    float v0 = p[tid];
    float v1 = p[tid + 256];
    float m = fmaxf(v0, v1);
#pragma unroll
    for (int o = 16; o; o >>= 1) m = fmaxf(m, __shfl_xor_sync(0xffffffffu, m, o));
    if ((tid & 31) == 0) redm[tid >> 5] = m;
    __syncthreads();
    float mAll = redm[0];
#pragma unroll
    for (int w = 1; w < 8; w++) mAll = fmaxf(mAll, redm[w]);

    float e0 = expf(v0 - mAll);
    float e1 = expf(v1 - mAll);
    float s = e0 + e1;
#pragma unroll
    for (int o = 16; o; o >>= 1) s += __shfl_xor_sync(0xffffffffu, s, o);
    if ((tid & 31) == 0) reds[tid >> 5] = s;
    __syncthreads();
    float sAll = 0.0f;
#pragma unroll
    for (int w = 0; w < 8; w++) sAll += reds[w];
    const float inv = 1.0f / sAll;
    p[tid] = e0 * inv;
    p[tid + 256] = e1 * inv;
}

// ---------------- launcher (unchanged, passing) ----------------
extern "C" void kernel_launch(void* const* d_in, const int* in_sizes, int n_in,
                              void* d_out, int out_size) {
    (void)in_sizes; (void)n_in;
    const float* x   = (const float*)d_in[0];
    const float* wqs = (const float*)d_in[1];
    // d_in[2] = w_ks: unused in reference math (faithful to source bug)
    float* out = (float*)d_out;

    const long long EAGG = (long long)NBATCH * TT * TD;  // 33,554,432
    const long long ATTN = (long long)NBATCH * TT * TT;  // 16,777,216

    float* attn;
    if ((long long)out_size >= EAGG + ATTN) {
        attn = out + EAGG;
    } else {
        void* p = nullptr;
        cudaGetSymbolAddress(&p, g_attn_fb);
        attn = (float*)p;
    }
    void* wqp = nullptr;
    cudaGetSymbolAddress(&wqp, g_wq);
    float* wq = (float*)wqp;

    // GEMM1: wq = x @ w_qs
    k_gemm_tf32<1><<<dim3(TH / 128, TT / 128, NBATCH), 256>>>(x, wqs, wq);
    // GEMM2: logits = wq @ wq^T
    k_gemm_tf32<2><<<dim3(TT / 128, TT / 128, NBATCH), 256>>>(wq, wq, attn);
    // softmax in place
    k_softmax<<<NBATCH * TT, 256>>>(attn);
    // GEMM3: e = attn @ x
    k_gemm_tf32<3><<<dim3(TD / 128, TT / 128, NBATCH), 256>>>(attn, x, out);
}

// round 9
// speedup vs baseline: 2.3653x; 1.6907x over previous
#include <cuda_runtime.h>
#include <cstdint>

// Problem dims (fixed by reference setup_inputs)
#define TB 4      // batch
#define TT 512    // tokens
#define TD 1024   // d_model
#define TNC 16    // n_concepts
#define TH 256    // init_size
#define NBATCH (TB * TNC)   // 64 batched GEMMs

// ---------------- scratch (__device__ globals; allocation-free rule) ----------------
__device__ float g_wq[(size_t)NBATCH * TT * TH];      // fp32 wq[z][t][h]
__device__ float g_attn_fb[(size_t)NBATCH * TT * TT]; // fp32 attn if d_out has no slot

// ---------------- helpers ----------------
__device__ __forceinline__ uint32_t smem_u32(const void* p) {
    uint32_t a;
    asm("{ .reg .u64 t; cvta.to.shared.u64 t, %1; cvt.u32.u64 %0, t; }" : "=r"(a) : "l"(p));
    return a;
}
__device__ __forceinline__ void cp16(uint32_t dst, const void* src) {
    asm volatile("cp.async.cg.shared.global [%0], [%1], 16;" :: "r"(dst), "l"(src) : "memory");
}
__device__ __forceinline__ void cp_commit() { asm volatile("cp.async.commit_group;" ::: "memory"); }
__device__ __forceinline__ void cp_wait0()  { asm volatile("cp.async.wait_group 0;" ::: "memory"); }

// bf16 hi/lo split of a k-adjacent fp32 pair -> packed bf16x2 regs (lo half = even k)
__device__ __forceinline__ void bf16_pack_split(float f0, float f1, uint32_t& hi, uint32_t& lo) {
    uint32_t h;
    asm("cvt.rn.bf16x2.f32 %0, %1, %2;" : "=r"(h) : "f"(f1), "f"(f0));  // hi-half=f1, lo-half=f0
    const float h0 = __uint_as_float(h << 16);
    const float h1 = __uint_as_float(h & 0xFFFF0000u);
    const float l0 = f0 - h0;
    const float l1 = f1 - h1;
    asm("cvt.rn.bf16x2.f32 %0, %1, %2;" : "=r"(lo) : "f"(l1), "f"(l0));
    hi = h;
}
__device__ __forceinline__ void mma_bf16(float* d, const uint32_t* a, const uint32_t* b) {
    asm volatile(
        "mma.sync.aligned.m16n8k16.row.col.f32.bf16.bf16.f32 "
        "{%0,%1,%2,%3}, {%4,%5,%6,%7}, {%8,%9}, {%0,%1,%2,%3};"
        : "+f"(d[0]), "+f"(d[1]), "+f"(d[2]), "+f"(d[3])
        : "r"(a[0]), "r"(a[1]), "r"(a[2]), "r"(a[3]), "r"(b[0]), "r"(b[1]));
}

// ---------------- bf16x3 batched GEMM: C tile 128x128 = A[M,K] * B(k,n) ----------------
// SMEM holds raw fp32 (cp.async direct); bf16 hi/lo split happens in registers at
// fragment-load time. A (and BTR B) rows padded to 24 floats -> conflict-free LDS.64
// for the stride-2lq k-pair pattern; direct B padded to 132 -> conflict-free LDS.32.
template <int MODE>
__global__ __launch_bounds__(256) void k_gemm_bf16(const float* __restrict__ Ain,
                                                   const float* __restrict__ Bin,
                                                   float* __restrict__ Cout) {
    constexpr int K   = (MODE == 1) ? TD : (MODE == 2) ? TH : TT;
    constexpr int NKB = K / 16;
    constexpr int LDA = K;
    constexpr int LDB = (MODE == 1) ? TH : (MODE == 2) ? TH : TD;
    constexpr int LDC = (MODE == 1) ? TH : (MODE == 2) ? TT : TD;
    constexpr bool BTR = (MODE == 2);          // B stored [n][k]
    constexpr int BR = BTR ? 128 : 16;
    constexpr int BC = BTR ? 24  : 132;

    __shared__ float sA[2][128][24];
    __shared__ float sB[2][BR][BC];

    const int tid = threadIdx.x, wid = tid >> 5, lane = tid & 31;
    const int wm = wid & 1, wn = wid >> 1;     // 2x4 warp grid, warp tile 64x32
    const int lr = lane >> 2, lq = lane & 3;
    const int z = blockIdx.z;
    const int m0 = blockIdx.y * 128;
    const int n0 = blockIdx.x * 128;

    size_t aoff, boff;
    if constexpr (MODE == 1) {
        aoff = (size_t)(z >> 4) * TT * TD;
        boff = (size_t)(z & 15) * TD * TH;
    } else if constexpr (MODE == 2) {
        aoff = (size_t)z * TT * TH;
        boff = aoff;
    } else {
        aoff = (size_t)z * TT * TT;
        boff = (size_t)(z >> 4) * TT * TD;
    }
    const float* pA = Ain + aoff + (size_t)m0 * LDA;
    const float* pB = BTR ? (Bin + boff + (size_t)n0 * LDB)   // [n][k] row offset
                          : (Bin + boff + n0);                // [k][n] col offset

    float acc[4][4][4];
#pragma unroll
    for (int mi = 0; mi < 4; mi++)
#pragma unroll
        for (int ni = 0; ni < 4; ni++)
#pragma unroll
            for (int e = 0; e < 4; e++) acc[mi][ni][e] = 0.0f;

    auto issue_stage = [&](int kb, int s) {
#pragma unroll
        for (int i = 0; i < 2; i++) {
            const int cid = tid + i * 256;
            const int ar = cid >> 2, ac4 = cid & 3;
            cp16(smem_u32(&sA[s][ar][ac4 * 4]),
                 pA + (size_t)ar * LDA + kb * 16 + ac4 * 4);
            if constexpr (BTR) {
                const int nr = cid >> 2, kc4 = cid & 3;
                cp16(smem_u32(&sB[s][nr][kc4 * 4]),
                     pB + (size_t)nr * LDB + kb * 16 + kc4 * 4);
            } else {
                const int kr = cid >> 5, nc4 = cid & 31;
                cp16(smem_u32(&sB[s][kr][nc4 * 4]),
                     pB + (size_t)(kb * 16 + kr) * LDB + nc4 * 4);
            }
        }
        cp_commit();
    };

    issue_stage(0, 0);

#pragma unroll 1
    for (int kb = 0; kb < NKB; kb++) {
        const int s = kb & 1;
        cp_wait0();
        __syncthreads();
        if (kb + 1 < NKB) issue_stage(kb + 1, s ^ 1);

        // ---- fragment load + in-register bf16 hi/lo split (one k16 group) ----
        uint32_t ah[4][4], al[4][4], bh[4][2], bl[4][2];
#pragma unroll
        for (int mi = 0; mi < 4; mi++) {
            const int row = wm * 64 + mi * 16 + lr;
            const float2 v0 = *reinterpret_cast<const float2*>(&sA[s][row][2 * lq]);
            const float2 v1 = *reinterpret_cast<const float2*>(&sA[s][row + 8][2 * lq]);
            const float2 v2 = *reinterpret_cast<const float2*>(&sA[s][row][2 * lq + 8]);
            const float2 v3 = *reinterpret_cast<const float2*>(&sA[s][row + 8][2 * lq + 8]);
            bf16_pack_split(v0.x, v0.y, ah[mi][0], al[mi][0]);
            bf16_pack_split(v1.x, v1.y, ah[mi][1], al[mi][1]);
            bf16_pack_split(v2.x, v2.y, ah[mi][2], al[mi][2]);
            bf16_pack_split(v3.x, v3.y, ah[mi][3], al[mi][3]);
        }
#pragma unroll
        for (int ni = 0; ni < 4; ni++) {
            const int n = wn * 32 + ni * 8 + lr;
            float f0, f1, f2, f3;
            if constexpr (BTR) {
                const float2 u0 = *reinterpret_cast<const float2*>(&sB[s][n][2 * lq]);
                const float2 u1 = *reinterpret_cast<const float2*>(&sB[s][n][2 * lq + 8]);
                f0 = u0.x; f1 = u0.y; f2 = u1.x; f3 = u1.y;
            } else {
                f0 = sB[s][2 * lq][n];     f1 = sB[s][2 * lq + 1][n];
                f2 = sB[s][2 * lq + 8][n]; f3 = sB[s][2 * lq + 9][n];
            }
            bf16_pack_split(f0, f1, bh[ni][0], bl[ni][0]);
            bf16_pack_split(f2, f3, bh[ni][1], bl[ni][1]);
        }

        // pass-major MMA ordering: dependent acc updates are 16 MMAs apart
#pragma unroll
        for (int mi = 0; mi < 4; mi++)
#pragma unroll
            for (int ni = 0; ni < 4; ni++)
                mma_bf16(acc[mi][ni], ah[mi], bh[ni]);   // hi*hi
#pragma unroll
        for (int mi = 0; mi < 4; mi++)
#pragma unroll
            for (int ni = 0; ni < 4; ni++)
                mma_bf16(acc[mi][ni], ah[mi], bl[ni]);   // hi*lo
#pragma unroll
        for (int mi = 0; mi < 4; mi++)
#pragma unroll
            for (int ni = 0; ni < 4; ni++)
                mma_bf16(acc[mi][ni], al[mi], bh[ni]);   // lo*hi
    }

    // ---- epilogue: fp32 float2 stores (identical to passing R8) ----
    const int rbase = m0 + wm * 64 + lr;
    const int cbase = n0 + wn * 32 + lq * 2;
#pragma unroll
    for (int mi = 0; mi < 4; mi++)
#pragma unroll
        for (int ni = 0; ni < 4; ni++)
#pragma unroll
            for (int h = 0; h < 2; h++) {
                const int row = rbase + mi * 16 + h * 8;
                const int col = cbase + ni * 8;
                float* dst = Cout + (size_t)z * TT * LDC + (size_t)row * LDC + col;
                *reinterpret_cast<float2*>(dst) =
                    make_float2(acc[mi][ni][2 * h], acc[mi][ni][2 * h + 1]);
            }
}

// ---------------- softmax over rows of 512 (unchanged, passing) ----------------
__global__ __launch_bounds__(256) void k_softmax(float* __restrict__ attn) {
    __shared__ float redm[8];
    __shared__ float reds[8];
    float* p = attn + (size_t)blockIdx.x * TT;
    const int tid = threadIdx.x;

    float v0 = p[tid];
    float v1 = p[tid + 256];
    float m = fmaxf(v0, v1);
#pragma unroll
    for (int o = 16; o; o >>= 1) m = fmaxf(m, __shfl_xor_sync(0xffffffffu, m, o));
    if ((tid & 31) == 0) redm[tid >> 5] = m;
    __syncthreads();
    float mAll = redm[0];
#pragma unroll
    for (int w = 1; w < 8; w++) mAll = fmaxf(mAll, redm[w]);

    float e0 = expf(v0 - mAll);
    float e1 = expf(v1 - mAll);
    float s = e0 + e1;
#pragma unroll
    for (int o = 16; o; o >>= 1) s += __shfl_xor_sync(0xffffffffu, s, o);
    if ((tid & 31) == 0) reds[tid >> 5] = s;
    __syncthreads();
    float sAll = 0.0f;
#pragma unroll
    for (int w = 0; w < 8; w++) sAll += reds[w];
    const float inv = 1.0f / sAll;
    p[tid] = e0 * inv;
    p[tid + 256] = e1 * inv;
}

// ---------------- launcher (unchanged, passing) ----------------
extern "C" void kernel_launch(void* const* d_in, const int* in_sizes, int n_in,
                              void* d_out, int out_size) {
    (void)in_sizes; (void)n_in;
    const float* x   = (const float*)d_in[0];
    const float* wqs = (const float*)d_in[1];
    // d_in[2] = w_ks: unused in reference math (faithful to source bug)
    float* out = (float*)d_out;

    const long long EAGG = (long long)NBATCH * TT * TD;  // 33,554,432
    const long long ATTN = (long long)NBATCH * TT * TT;  // 16,777,216

    float* attn;
    if ((long long)out_size >= EAGG + ATTN) {
        attn = out + EAGG;
    } else {
        void* p = nullptr;
        cudaGetSymbolAddress(&p, g_attn_fb);
        attn = (float*)p;
    }
    void* wqp = nullptr;
    cudaGetSymbolAddress(&wqp, g_wq);
    float* wq = (float*)wqp;

    // GEMM1: wq = x @ w_qs
    k_gemm_bf16<1><<<dim3(TH / 128, TT / 128, NBATCH), 256>>>(x, wqs, wq);
    // GEMM2: logits = wq @ wq^T
    k_gemm_bf16<2><<<dim3(TT / 128, TT / 128, NBATCH), 256>>>(wq, wq, attn);
    // softmax in place
    k_softmax<<<NBATCH * TT, 256>>>(attn);
    // GEMM3: e = attn @ x
    k_gemm_bf16<3><<<dim3(TD / 128, TT / 128, NBATCH), 256>>>(attn, x, out);
}